// round 15
// baseline (speedup 1.0000x reference)
#include <cuda_runtime.h>
#include <cuda_fp16.h>
#include <math.h>
#include <stdint.h>

#define NB   8
#define DIM  192
#define ST   64
#define HWSZ 4096
#define TOK  (NB*HWSZ)
#define HID  768
#define CHL  8
#define NCH  (HWSZ/CHL)     // 512
#define PITCHH 72           // smem row pitch in halfs (144B) -> conflict-free ldmatrix

// ---------------- scratch ----------------
__device__ __align__(16) __half g_xn1[TOK*DIM];
__device__ __align__(16) __half g_xn2[TOK*DIM];
__device__ __align__(16) __half g_proj[TOK*256];
__device__ float g_Av[TOK*ST];
__device__ float g_h[TOK*ST];
__device__ __align__(16) __half g_yh[TOK*ST];
__device__ float g_ssm[(size_t)TOK*DIM];
__device__ float g_xr[(size_t)TOK*DIM];
__device__ __align__(16) __half g_xn3[TOK*DIM];
__device__ __align__(16) __half g_hid[(size_t)TOK*HID];
__device__ __align__(16) __half g_wcat[256*DIM];
__device__ __align__(16) __half g_wout[DIM*ST];
__device__ __align__(16) __half g_w1[HID*DIM];
__device__ __align__(16) __half g_w2[DIM*HID];
__device__ float g_bias256[256];
__device__ float g_Aneg[ST];
__device__ float g_P[NB*NCH*ST];
__device__ float g_hend[NB*NCH*ST];
__device__ float g_hin[NB*NCH*ST];

// ---------------- helpers ----------------
__device__ __forceinline__ void cp16(void* dst_smem, const void* src)
{
    uint32_t d = (uint32_t)__cvta_generic_to_shared(dst_smem);
    asm volatile("cp.async.cg.shared.global [%0], [%1], 16;" :: "r"(d), "l"(src));
}
__device__ __forceinline__ void cp_commit() { asm volatile("cp.async.commit_group;"); }
template<int W> __device__ __forceinline__ void cp_wait() { asm volatile("cp.async.wait_group %0;" :: "n"(W)); }

__device__ __forceinline__ void ldm4(uint32_t* r, const void* smem)
{
    uint32_t a = (uint32_t)__cvta_generic_to_shared(smem);
    asm volatile("ldmatrix.sync.aligned.m8n8.x4.shared.b16 {%0,%1,%2,%3}, [%4];"
                 : "=r"(r[0]), "=r"(r[1]), "=r"(r[2]), "=r"(r[3]) : "r"(a));
}
__device__ __forceinline__ void mma_f16(float* c, const uint32_t* a, const uint32_t* b)
{
    asm volatile("mma.sync.aligned.m16n8k16.row.col.f32.f16.f16.f32 "
        "{%0,%1,%2,%3}, {%4,%5,%6,%7}, {%8,%9}, {%0,%1,%2,%3};"
        : "+f"(c[0]), "+f"(c[1]), "+f"(c[2]), "+f"(c[3])
        : "r"(a[0]), "r"(a[1]), "r"(a[2]), "r"(a[3]), "r"(b[0]), "r"(b[1]));
}

// ---------------- prep ----------------
__global__ void k_prep(const float* __restrict__ dt_w, const float* __restrict__ B_w,
                       const float* __restrict__ C_w,  const float* __restrict__ xp_w,
                       const float* __restrict__ dt_b, const float* __restrict__ xp_b,
                       const float* __restrict__ A_log, const float* __restrict__ out_w,
                       const float* __restrict__ mlp_w1, const float* __restrict__ mlp_w2)
{
    int i = blockIdx.x * blockDim.x + threadIdx.x;
    if (i < 256*DIM) {
        int n = i / DIM, k = i - n*DIM;
        float v;
        if      (n < 64)  v = dt_w[n*DIM + k];
        else if (n < 128) v = B_w[(n-64)*DIM + k];
        else if (n < 192) v = C_w[(n-128)*DIM + k];
        else              v = xp_w[(n-192)*DIM + k];
        g_wcat[i] = __float2half(v);
    }
    if (i < DIM*ST)  g_wout[i] = __float2half(out_w[i]);
    if (i < HID*DIM) { g_w1[i] = __float2half(mlp_w1[i]); g_w2[i] = __float2half(mlp_w2[i]); }
    if (i < 256) {
        float b = 0.f;
        if (i < 64)        b = dt_b[i];
        else if (i >= 192) b = xp_b[i-192];
        g_bias256[i] = b;
    }
    if (i < ST) g_Aneg[i] = -expf(A_log[i]);
}

// ---------------- LayerNorm (coalesced, 32 tok/block) ----------------
template<int MODE>
__global__ void __launch_bounds__(1024) k_ln(const float* __restrict__ xin,
                     const float* __restrict__ g1, const float* __restrict__ b1,
                     const float* __restrict__ g2, const float* __restrict__ b2,
                     const float* __restrict__ dw,
                     const float* __restrict__ bn_g, const float* __restrict__ bn_b,
                     const float* __restrict__ bn_rm, const float* __restrict__ bn_rv,
                     const float* __restrict__ aL, const float* __restrict__ aS)
{
    __shared__ float s[192*33];
    int tid = threadIdx.x;
    int tok0 = blockIdx.x * 32;
    int b = tok0 >> 12, hw0 = tok0 & (HWSZ-1);

    if (MODE == 0) {
        #pragma unroll
        for (int i = 0; i < 6; i++) {
            int idx = tid + 1024*i;
            int c = idx >> 5, j = idx & 31;
            s[c*33 + j] = xin[((size_t)(b*DIM + c))*HWSZ + hw0 + j];
        }
    } else {
        int h = hw0 >> 6, w0 = hw0 & 63;
        float aLv = aL[0], aSv = aS[0];
        #pragma unroll
        for (int i = 0; i < 6; i++) {
            int idx = tid + 1024*i;
            int c = idx >> 5, j = idx & 31;
            int w = w0 + j;
            const float* xb = xin + ((size_t)(b*DIM + c))*HWSZ;
            const float* wk = dw + c*9;
            float acc = 0.f;
            #pragma unroll
            for (int kh = 0; kh < 3; kh++) {
                int hh = h + kh - 1;
                if (hh < 0 || hh >= 64) continue;
                #pragma unroll
                for (int kw = 0; kw < 3; kw++) {
                    int ww = w + kw - 1;
                    if (ww < 0 || ww >= 64) continue;
                    acc += xb[hh*64 + ww] * wk[kh*3 + kw];
                }
            }
            float scale = bn_g[c] * rsqrtf(bn_rv[c] + 1e-5f);
            float local = (acc - bn_rm[c]) * scale + bn_b[c];
            size_t base = ((size_t)(b*DIM + c))*HWSZ + h*64 + w;
            float xr = xb[h*64 + w] + aLv*local + aSv*g_ssm[base];
            g_xr[base] = xr;
            s[c*33 + j] = xr;
        }
    }
    __syncthreads();
    int w = tid >> 5, l = tid & 31;
    float v[6], sum = 0.f, sq = 0.f;
    #pragma unroll
    for (int i = 0; i < 6; i++) { v[i] = s[(l + 32*i)*33 + w]; sum += v[i]; sq += v[i]*v[i]; }
    #pragma unroll
    for (int o = 16; o > 0; o >>= 1) {
        sum += __shfl_xor_sync(0xffffffffu, sum, o);
        sq  += __shfl_xor_sync(0xffffffffu, sq,  o);
    }
    float mean = sum * (1.f/DIM), var = sq * (1.f/DIM) - mean*mean;
    float rs = rsqrtf(var + 1e-5f);
    float y[6];
    #pragma unroll
    for (int i = 0; i < 6; i++) { int c = l + 32*i; y[i] = (v[i] - mean) * rs * g1[c] + b1[c]; }
    __syncthreads();
    #pragma unroll
    for (int i = 0; i < 6; i++) s[(l + 32*i)*33 + w] = y[i];
    __syncthreads();
    #pragma unroll
    for (int i = 0; i < 6; i++) {
        int idx = tid + 1024*i;
        int tok = idx / 192, c = idx - tok*192;
        float val = s[c*33 + tok];
        if (MODE == 0) g_xn1[(size_t)(tok0 + tok)*DIM + c] = __float2half(val);
        else           g_xn3[(size_t)(tok0 + tok)*DIM + c] = __float2half(val);
    }
    if (MODE == 0) {
        float s2a = 0.f, s2b = 0.f;
        #pragma unroll
        for (int i = 0; i < 6; i++) { s2a += y[i]; s2b += y[i]*y[i]; }
        #pragma unroll
        for (int o = 16; o > 0; o >>= 1) {
            s2a += __shfl_xor_sync(0xffffffffu, s2a, o);
            s2b += __shfl_xor_sync(0xffffffffu, s2b, o);
        }
        float m2 = s2a * (1.f/DIM), v2 = s2b * (1.f/DIM) - m2*m2;
        float rs2 = rsqrtf(v2 + 1e-5f);
        __syncthreads();
        #pragma unroll
        for (int i = 0; i < 6; i++) { int c = l + 32*i; s[(l + 32*i)*33 + w] = (y[i] - m2) * rs2 * g2[c] + b2[c]; }
        __syncthreads();
        #pragma unroll
        for (int i = 0; i < 6; i++) {
            int idx = tid + 1024*i;
            int tok = idx / 192, c = idx - tok*192;
            g_xn2[(size_t)(tok0 + tok)*DIM + c] = __float2half(s[c*33 + tok]);
        }
    }
}

// ---------------- scan pass 1 ----------------
__global__ void __launch_bounds__(256) k_scan1()
{
    int s = threadIdx.x;
    int bidx = blockIdx.x*4 + threadIdx.y;
    int b = bidx >> 9, ch = bidx & (NCH-1);
    float An = g_Aneg[s];
    float h = 0.f, P = 1.f;
    int tok0 = b*HWSZ + ch*CHL;
    bool c0 = (ch == 0);
    #pragma unroll
    for (int t = 0; t < CHL; t++) {
        const __half* p = g_proj + (size_t)(tok0 + t)*256;
        float dt = __half2float(p[s]);
        float Bv = __half2float(p[64+s]);
        float xv = __half2float(p[192+s]);
        float sp = fmaxf(dt, 0.f) + log1pf(expf(-fabsf(dt)));
        float delta = sp * 0.01f + 1e-4f;
        float dA = fminf(fmaxf(delta * An, -10.f), -1e-4f);
        float Av = fminf(fmaxf(expf(dA), 0.001f), 0.999f);
        float BX = delta * Bv * xv;
        h = (c0 && t == 0) ? BX : Av*(h + BX);
        P *= Av;
        size_t o = (size_t)(tok0 + t)*ST + s;
        g_h[o] = h;
        g_Av[o] = Av;
    }
    g_P[bidx*ST + s] = P;
    g_hend[bidx*ST + s] = h;
}

// ---------------- scan pass 2 ----------------
__global__ void __launch_bounds__(256) k_scan2()
{
    int gw = blockIdx.x*8 + (threadIdx.x >> 5);
    int lane = threadIdx.x & 31;
    int b = gw >> 6, s = gw & 63;
    int base = (b*NCH)*ST + s;

    float P[16], E[16];
    #pragma unroll
    for (int j = 0; j < 16; j++) {
        int ch = lane*16 + j;
        P[j] = g_P[base + ch*ST];
        E[j] = g_hend[base + ch*ST];
    }
    float tP = 1.f, tE = 0.f;
    #pragma unroll
    for (int j = 0; j < 16; j++) { float nP = P[j]*tP, nE = P[j]*tE + E[j]; tP = nP; tE = nE; }
    float sP = tP, sE = tE;
    #pragma unroll
    for (int off = 1; off < 32; off <<= 1) {
        float pP = __shfl_up_sync(0xffffffffu, sP, off);
        float pE = __shfl_up_sync(0xffffffffu, sE, off);
        if (lane >= off) { sE = sP*pE + sE; sP = sP*pP; }
    }
    float eP = __shfl_up_sync(0xffffffffu, sP, 1);
    float eE = __shfl_up_sync(0xffffffffu, sE, 1);
    if (lane == 0) { eP = 1.f; eE = 0.f; }
    float hP = eP, hE = eE;
    #pragma unroll
    for (int j = 0; j < 16; j++) {
        int ch = lane*16 + j;
        g_hin[base + ch*ST] = hE;
        float nP = P[j]*hP, nE = P[j]*hE + E[j];
        hP = nP; hE = nE;
    }
}

// ---------------- scan pass 3 ----------------
__global__ void __launch_bounds__(256) k_scan3()
{
    int s = threadIdx.x;
    int bidx = blockIdx.x*4 + threadIdx.y;
    int b = bidx >> 9, ch = bidx & (NCH-1);
    float hin = g_hin[bidx*ST + s];
    float P = 1.f;
    int tok0 = b*HWSZ + ch*CHL;
    #pragma unroll
    for (int t = 0; t < CHL; t++) {
        size_t o = (size_t)(tok0 + t)*ST + s;
        P *= g_Av[o];
        float hf = g_h[o] + P*hin;
        float Cv = __half2float(g_proj[(size_t)(tok0 + t)*256 + 128 + s]);
        g_yh[o] = __float2half(Cv * hf);
    }
}

// ---------------- multi-row-tile GEMM, B resident in smem (K <= 192) ----------------
// C[M,N] = A[M,K] @ Bw[N,K]^T. BM=128, BN=64. Block processes RT row-tiles.
// EPI 0: A=g_xn2, B=g_wcat -> g_proj (half)
// EPI 1: A=g_yh,  B=g_wout + D*xn1 -> g_ssm (NCHW float)
// EPI 2: A=g_xn3, B=g_w1 + gelu -> g_hid (half)
#define ASTAGEH (128*PITCHH)
template<int EPI, int N, int K, int RT>
__global__ void __launch_bounds__(256, 2) k_mmaT(const float* __restrict__ bias,
                                                 const float* __restrict__ Dp)
{
    constexpr int NKs = K / 64;
    extern __shared__ char smc[];
    __half* Bf = reinterpret_cast<__half*>(smc);                 // NKs * 64*PITCHH
    __half* Ast = Bf + NKs*64*PITCHH;                            // 2 * ASTAGEH
    float* T = reinterpret_cast<float*>(Ast + 2*ASTAGEH);        // EPI1 epilogue staging
    const __half* A  = (EPI == 0) ? g_xn2 : (EPI == 1) ? g_yh : g_xn3;
    const __half* Bp = (EPI == 0) ? g_wcat : (EPI == 1) ? g_wout : g_w1;
    const float* bp = (EPI == 0) ? g_bias256 : bias;

    int tid = threadIdx.x;
    int wid = tid >> 5, lane = tid & 31;
    int g = lane >> 2, t4 = lane & 3;
    int rowbase = blockIdx.y * (128*RT), col0 = blockIdx.x * 64;
    int m0 = (wid & 3) * 32, n0 = (wid >> 2) * 32;
    int lrow = lane & 7, lmat = lane >> 3;
    int a_moff = (lmat & 1)*8, a_koff = (lmat >> 1)*8;
    int b_noff = (lmat >> 1)*8, b_koff = (lmat & 1)*8;

    float acc[2][4][4];
    #pragma unroll
    for (int mi = 0; mi < 2; mi++)
        #pragma unroll
        for (int ni = 0; ni < 4; ni++)
            #pragma unroll
            for (int e = 0; e < 4; e++) acc[mi][ni][e] = 0.f;

    // resident B: all NKs slabs
    for (int idx = tid; idx < NKs*64*8; idx += 256) {
        int slab = idx >> 9, rem = idx & 511;
        int n = rem >> 3, c = rem & 7;
        cp16(Bf + slab*(64*PITCHH) + n*PITCHH + c*8,
             Bp + (size_t)(col0 + n)*K + slab*64 + c*8);
    }
    auto loadA = [&](int i, int st) {     // flattened slab i
        int t = i / NKs, kt = i - t*NKs;
        int row0 = rowbase + t*128;
        int k0 = kt*64;
        __half* As = Ast + st*ASTAGEH;
        #pragma unroll
        for (int j = 0; j < 4; j++) {
            int idx = tid + 256*j;
            int m = idx >> 3, c = idx & 7;
            cp16(As + m*PITCHH + c*8, A + (size_t)(row0 + m)*K + k0 + c*8);
        }
    };
    const int TOT = RT * NKs;
    loadA(0, 0);
    cp_commit();
    for (int i = 0; i < TOT; i++) {
        if (i + 1 < TOT) { loadA(i + 1, (i + 1) & 1); cp_commit(); cp_wait<1>(); }
        else cp_wait<0>();
        __syncthreads();
        const __half* As = Ast + (i & 1)*ASTAGEH;
        const __half* Bs = Bf + (i % NKs)*(64*PITCHH);
        #pragma unroll
        for (int ks = 0; ks < 4; ks++) {
            int kb = ks*16;
            uint32_t a[2][4], b[2][4];
            #pragma unroll
            for (int mi = 0; mi < 2; mi++)
                ldm4(a[mi], As + (m0 + mi*16 + lrow + a_moff)*PITCHH + kb + a_koff);
            #pragma unroll
            for (int nb = 0; nb < 2; nb++)
                ldm4(b[nb], Bs + (n0 + nb*16 + lrow + b_noff)*PITCHH + kb + b_koff);
            #pragma unroll
            for (int mi = 0; mi < 2; mi++)
                #pragma unroll
                for (int ni = 0; ni < 4; ni++)
                    mma_f16(acc[mi][ni], a[mi], &b[ni >> 1][(ni & 1)*2]);
        }
        __syncthreads();

        if ((i + 1) % NKs == 0) {
            int row0 = rowbase + (i / NKs)*128;
            if (EPI == 0 || EPI == 2) {
                #pragma unroll
                for (int mi = 0; mi < 2; mi++)
                    #pragma unroll
                    for (int ni = 0; ni < 4; ni++)
                        #pragma unroll
                        for (int e = 0; e < 4; e++) {
                            int m = row0 + m0 + mi*16 + g + ((e >> 1) << 3);
                            int n = col0 + n0 + ni*8 + t4*2 + (e & 1);
                            float v = acc[mi][ni][e] + bp[n];
                            if (EPI == 2) {
                                v = 0.5f * v * (1.f + erff(v * 0.7071067811865476f));
                                g_hid[(size_t)m*N + n] = __float2half(v);
                            } else {
                                g_proj[(size_t)m*N + n] = __float2half(v);
                            }
                        }
            } else {
                #pragma unroll
                for (int mi = 0; mi < 2; mi++)
                    #pragma unroll
                    for (int ni = 0; ni < 4; ni++)
                        #pragma unroll
                        for (int e = 0; e < 4; e++) {
                            int ml = m0 + mi*16 + g + ((e >> 1) << 3);
                            int nl = n0 + ni*8 + t4*2 + (e & 1);
                            int n = col0 + nl;
                            float v = acc[mi][ni][e] + bp[n];
                            float d = fminf(fmaxf(Dp[n], -2.f), 2.f);
                            v += d * __half2float(g_xn1[(size_t)(row0 + ml)*DIM + n]);
                            T[nl*129 + ml] = v;
                        }
                __syncthreads();
                int bb = row0 >> 12, hw0 = row0 & (HWSZ-1);
                #pragma unroll
                for (int j = 0; j < 32; j++) {
                    int idx = tid + 256*j;
                    int nl = idx >> 7, ml = idx & 127;
                    g_ssm[((size_t)(bb*DIM + col0 + nl))*HWSZ + hw0 + ml] = T[nl*129 + ml];
                }
            }
            #pragma unroll
            for (int mi = 0; mi < 2; mi++)
                #pragma unroll
                for (int ni = 0; ni < 4; ni++)
                    #pragma unroll
                    for (int e = 0; e < 4; e++) acc[mi][ni][e] = 0.f;
        }
    }
}

// ---------------- fc2: 3-stage pipeline (K=768, B not cacheable) ----------------
#define STAGEH ((128 + 64) * PITCHH)
__global__ void __launch_bounds__(256, 2) k_mma3(const float* __restrict__ bias,
                                                 const float* __restrict__ alpha,
                                                 float* __restrict__ Cout)
{
    constexpr int N = 192, K = HID;
    extern __shared__ char smc[];
    __half* stage0 = reinterpret_cast<__half*>(smc);
    const __half* A = g_hid;
    const __half* Bp = g_w2;

    int tid = threadIdx.x;
    int wid = tid >> 5, lane = tid & 31;
    int g = lane >> 2, t4 = lane & 3;
    int row0 = blockIdx.y * 128, col0 = blockIdx.x * 64;
    int m0 = (wid & 3) * 32, n0 = (wid >> 2) * 32;
    int lrow = lane & 7, lmat = lane >> 3;
    int a_moff = (lmat & 1)*8, a_koff = (lmat >> 1)*8;
    int b_noff = (lmat >> 1)*8, b_koff = (lmat & 1)*8;

    float acc[2][4][4];
    #pragma unroll
    for (int mi = 0; mi < 2; mi++)
        #pragma unroll
        for (int ni = 0; ni < 4; ni++)
            #pragma unroll
            for (int e = 0; e < 4; e++) acc[mi][ni][e] = 0.f;

    const int NK = K / 64;
    auto load_slab = [&](int kt, int st) {
        __half* As = stage0 + st*STAGEH;
        __half* Bs = As + 128*PITCHH;
        int k0 = kt * 64;
        #pragma unroll
        for (int i = 0; i < 4; i++) {
            int idx = tid + 256*i;
            int m = idx >> 3, c = idx & 7;
            cp16(As + m*PITCHH + c*8, A + (size_t)(row0 + m)*K + k0 + c*8);
        }
        #pragma unroll
        for (int i = 0; i < 2; i++) {
            int idx = tid + 256*i;
            int n = idx >> 3, c = idx & 7;
            cp16(Bs + n*PITCHH + c*8, Bp + (size_t)(col0 + n)*K + k0 + c*8);
        }
    };
    load_slab(0, 0);
    cp_commit();
    load_slab(1, 1);
    cp_commit();
    for (int kt = 0; kt < NK; kt++) {
        if (kt + 2 < NK) { load_slab(kt + 2, (kt + 2) % 3); cp_commit(); cp_wait<2>(); }
        else if (kt + 1 < NK) cp_wait<1>();
        else cp_wait<0>();
        __syncthreads();
        int cur = kt % 3;
        const __half* As = stage0 + cur*STAGEH;
        const __half* Bs = As + 128*PITCHH;
        #pragma unroll
        for (int ks = 0; ks < 4; ks++) {
            int kb = ks*16;
            uint32_t a[2][4], b[2][4];
            #pragma unroll
            for (int mi = 0; mi < 2; mi++)
                ldm4(a[mi], As + (m0 + mi*16 + lrow + a_moff)*PITCHH + kb + a_koff);
            #pragma unroll
            for (int nb = 0; nb < 2; nb++)
                ldm4(b[nb], Bs + (n0 + nb*16 + lrow + b_noff)*PITCHH + kb + b_koff);
            #pragma unroll
            for (int mi = 0; mi < 2; mi++)
                #pragma unroll
                for (int ni = 0; ni < 4; ni++)
                    mma_f16(acc[mi][ni], a[mi], &b[ni >> 1][(ni & 1)*2]);
        }
        __syncthreads();
    }

    float* T = reinterpret_cast<float*>(smc);
    __syncthreads();
    #pragma unroll
    for (int mi = 0; mi < 2; mi++)
        #pragma unroll
        for (int ni = 0; ni < 4; ni++)
            #pragma unroll
            for (int e = 0; e < 4; e++) {
                int ml = m0 + mi*16 + g + ((e >> 1) << 3);
                int nl = n0 + ni*8 + t4*2 + (e & 1);
                T[nl*129 + ml] = acc[mi][ni][e] + bias[col0 + nl];
            }
    __syncthreads();
    int bb = row0 >> 12, hw0 = row0 & (HWSZ-1);
    float av = alpha[0];
    #pragma unroll
    for (int i = 0; i < 32; i++) {
        int idx = tid + 256*i;
        int nl = idx >> 7, ml = idx & 127;
        size_t adr = ((size_t)(bb*DIM + col0 + nl))*HWSZ + hw0 + ml;
        Cout[adr] = g_xr[adr] + av * T[nl*129 + ml];
    }
}

// smem sizes
#define SMT(NKs) (((NKs)*64 + 2*128)*PITCHH*2)
#define SM_EPI0 SMT(3)
#define SM_EPI2 SMT(3)
#define SM_EPI1 (SMT(1) + 64*129*4)
#define SM_FC2_MAIN (3*STAGEH*2)
#define SM_FC2_T (64*129*4)
#define SM_FC2 (SM_FC2_MAIN > SM_FC2_T ? SM_FC2_MAIN : SM_FC2_T)

// ---------------- launch ----------------
extern "C" void kernel_launch(void* const* d_in, const int* in_sizes, int n_in,
                              void* d_out, int out_size)
{
    const float* x        = (const float*)d_in[0];
    const float* ln1_g    = (const float*)d_in[1];
    const float* ln1_b    = (const float*)d_in[2];
    const float* ln2_g    = (const float*)d_in[3];
    const float* ln2_b    = (const float*)d_in[4];
    const float* dw_w     = (const float*)d_in[5];
    const float* bn_g     = (const float*)d_in[6];
    const float* bn_b     = (const float*)d_in[7];
    const float* bn_rm    = (const float*)d_in[8];
    const float* bn_rv    = (const float*)d_in[9];
    const float* ssm_ln_g = (const float*)d_in[10];
    const float* ssm_ln_b = (const float*)d_in[11];
    const float* xp_w     = (const float*)d_in[12];
    const float* xp_b     = (const float*)d_in[13];
    const float* dt_w     = (const float*)d_in[14];
    const float* dt_b     = (const float*)d_in[15];
    const float* A_log    = (const float*)d_in[16];
    const float* B_w      = (const float*)d_in[17];
    const float* C_w      = (const float*)d_in[18];
    const float* D_param  = (const float*)d_in[19];
    const float* out_w    = (const float*)d_in[20];
    const float* out_b    = (const float*)d_in[21];
    const float* mlp_w1   = (const float*)d_in[22];
    const float* mlp_b1   = (const float*)d_in[23];
    const float* mlp_w2   = (const float*)d_in[24];
    const float* mlp_b2   = (const float*)d_in[25];
    const float* aL       = (const float*)d_in[26];
    const float* aS       = (const float*)d_in[27];
    const float* aM       = (const float*)d_in[28];
    float* out = (float*)d_out;

    cudaFuncSetAttribute(k_mmaT<0,256,192,4>, cudaFuncAttributeMaxDynamicSharedMemorySize, SM_EPI0);
    cudaFuncSetAttribute(k_mmaT<1,192,64,2>,  cudaFuncAttributeMaxDynamicSharedMemorySize, SM_EPI1);
    cudaFuncSetAttribute(k_mmaT<2,HID,192,8>, cudaFuncAttributeMaxDynamicSharedMemorySize, SM_EPI2);
    cudaFuncSetAttribute(k_mma3, cudaFuncAttributeMaxDynamicSharedMemorySize, SM_FC2);

    k_prep<<<576, 256>>>(dt_w, B_w, C_w, xp_w, dt_b, xp_b, A_log, out_w, mlp_w1, mlp_w2);
    k_ln<0><<<TOK/32, 1024>>>(x, ln1_g, ln1_b, ssm_ln_g, ssm_ln_b,
                              nullptr, nullptr, nullptr, nullptr, nullptr, nullptr, nullptr);
    k_mmaT<0, 256, 192, 4><<<dim3(4, 64), 256, SM_EPI0>>>(nullptr, nullptr);
    k_scan1<<<NB*NCH/4, dim3(64,4)>>>();
    k_scan2<<<64, 256>>>();
    k_scan3<<<NB*NCH/4, dim3(64,4)>>>();
    k_mmaT<1, 192, 64, 2><<<dim3(3, 128), 256, SM_EPI1>>>(out_b, D_param);
    k_ln<1><<<TOK/32, 1024>>>(x, ln2_g, ln2_b, nullptr, nullptr,
                              dw_w, bn_g, bn_b, bn_rm, bn_rv, aL, aS);
    k_mmaT<2, HID, 192, 8><<<dim3(12, 32), 256, SM_EPI2>>>(mlp_b1, nullptr);
    k_mma3<<<dim3(3, 256), 256, SM_FC2>>>(mlp_b2, aM, out);
}

// round 16
// speedup vs baseline: 1.0833x; 1.0833x over previous
#include <cuda_runtime.h>
#include <cuda_fp16.h>
#include <math.h>
#include <stdint.h>

#define NB   8
#define DIM  192
#define ST   64
#define HWSZ 4096
#define TOK  (NB*HWSZ)
#define HID  768
#define CHL  8
#define NCH  (HWSZ/CHL)     // 512
#define PITCHH 72           // smem row pitch in halfs (144B) -> conflict-free ldmatrix

// ---------------- scratch ----------------
__device__ __align__(16) __half g_xn1[TOK*DIM];
__device__ __align__(16) __half g_xn2[TOK*DIM];
__device__ __align__(16) __half g_proj[TOK*256];
__device__ __align__(16) float g_Pc[TOK*ST];     // cumulative prod of Av within chunk
__device__ __align__(16) float g_h[TOK*ST];
__device__ float g_ssm[(size_t)TOK*DIM];
__device__ float g_xr[(size_t)TOK*DIM];
__device__ __align__(16) __half g_xn3[TOK*DIM];
__device__ __align__(16) __half g_hid[(size_t)TOK*HID];
__device__ __align__(16) __half g_wcat[256*DIM];
__device__ __align__(16) __half g_wout[DIM*ST];
__device__ __align__(16) __half g_w1[HID*DIM];
__device__ __align__(16) __half g_w2[DIM*HID];
__device__ float g_bias256[256];
__device__ float g_Aneg[ST];
__device__ float g_P[NB*NCH*ST];
__device__ float g_hend[NB*NCH*ST];
__device__ __align__(16) float g_hin[NB*NCH*ST];

// ---------------- helpers ----------------
__device__ __forceinline__ void cp16(void* dst_smem, const void* src)
{
    uint32_t d = (uint32_t)__cvta_generic_to_shared(dst_smem);
    asm volatile("cp.async.cg.shared.global [%0], [%1], 16;" :: "r"(d), "l"(src));
}
__device__ __forceinline__ void cp_commit() { asm volatile("cp.async.commit_group;"); }
template<int W> __device__ __forceinline__ void cp_wait() { asm volatile("cp.async.wait_group %0;" :: "n"(W)); }

__device__ __forceinline__ void ldm4(uint32_t* r, const void* smem)
{
    uint32_t a = (uint32_t)__cvta_generic_to_shared(smem);
    asm volatile("ldmatrix.sync.aligned.m8n8.x4.shared.b16 {%0,%1,%2,%3}, [%4];"
                 : "=r"(r[0]), "=r"(r[1]), "=r"(r[2]), "=r"(r[3]) : "r"(a));
}
__device__ __forceinline__ void mma_f16(float* c, const uint32_t* a, const uint32_t* b)
{
    asm volatile("mma.sync.aligned.m16n8k16.row.col.f32.f16.f16.f32 "
        "{%0,%1,%2,%3}, {%4,%5,%6,%7}, {%8,%9}, {%0,%1,%2,%3};"
        : "+f"(c[0]), "+f"(c[1]), "+f"(c[2]), "+f"(c[3])
        : "r"(a[0]), "r"(a[1]), "r"(a[2]), "r"(a[3]), "r"(b[0]), "r"(b[1]));
}

// ---------------- prep ----------------
__global__ void k_prep(const float* __restrict__ dt_w, const float* __restrict__ B_w,
                       const float* __restrict__ C_w,  const float* __restrict__ xp_w,
                       const float* __restrict__ dt_b, const float* __restrict__ xp_b,
                       const float* __restrict__ A_log, const float* __restrict__ out_w,
                       const float* __restrict__ mlp_w1, const float* __restrict__ mlp_w2)
{
    int i = blockIdx.x * blockDim.x + threadIdx.x;
    if (i < 256*DIM) {
        int n = i / DIM, k = i - n*DIM;
        float v;
        if      (n < 64)  v = dt_w[n*DIM + k];
        else if (n < 128) v = B_w[(n-64)*DIM + k];
        else if (n < 192) v = C_w[(n-128)*DIM + k];
        else              v = xp_w[(n-192)*DIM + k];
        g_wcat[i] = __float2half(v);
    }
    if (i < DIM*ST)  g_wout[i] = __float2half(out_w[i]);
    if (i < HID*DIM) { g_w1[i] = __float2half(mlp_w1[i]); g_w2[i] = __float2half(mlp_w2[i]); }
    if (i < 256) {
        float b = 0.f;
        if (i < 64)        b = dt_b[i];
        else if (i >= 192) b = xp_b[i-192];
        g_bias256[i] = b;
    }
    if (i < ST) g_Aneg[i] = -expf(A_log[i]);
}

// ---------------- LayerNorm (coalesced, 32 tok/block) ----------------
template<int MODE>
__global__ void __launch_bounds__(1024) k_ln(const float* __restrict__ xin,
                     const float* __restrict__ g1, const float* __restrict__ b1,
                     const float* __restrict__ g2, const float* __restrict__ b2,
                     const float* __restrict__ dw,
                     const float* __restrict__ bn_g, const float* __restrict__ bn_b,
                     const float* __restrict__ bn_rm, const float* __restrict__ bn_rv,
                     const float* __restrict__ aL, const float* __restrict__ aS)
{
    __shared__ float s[192*33];
    int tid = threadIdx.x;
    int tok0 = blockIdx.x * 32;
    int b = tok0 >> 12, hw0 = tok0 & (HWSZ-1);

    if (MODE == 0) {
        #pragma unroll
        for (int i = 0; i < 6; i++) {
            int idx = tid + 1024*i;
            int c = idx >> 5, j = idx & 31;
            s[c*33 + j] = xin[((size_t)(b*DIM + c))*HWSZ + hw0 + j];
        }
    } else {
        int h = hw0 >> 6, w0 = hw0 & 63;
        float aLv = aL[0], aSv = aS[0];
        #pragma unroll
        for (int i = 0; i < 6; i++) {
            int idx = tid + 1024*i;
            int c = idx >> 5, j = idx & 31;
            int w = w0 + j;
            const float* xb = xin + ((size_t)(b*DIM + c))*HWSZ;
            const float* wk = dw + c*9;
            float acc = 0.f;
            #pragma unroll
            for (int kh = 0; kh < 3; kh++) {
                int hh = h + kh - 1;
                if (hh < 0 || hh >= 64) continue;
                #pragma unroll
                for (int kw = 0; kw < 3; kw++) {
                    int ww = w + kw - 1;
                    if (ww < 0 || ww >= 64) continue;
                    acc += xb[hh*64 + ww] * wk[kh*3 + kw];
                }
            }
            float scale = bn_g[c] * rsqrtf(bn_rv[c] + 1e-5f);
            float local = (acc - bn_rm[c]) * scale + bn_b[c];
            size_t base = ((size_t)(b*DIM + c))*HWSZ + h*64 + w;
            float xr = xb[h*64 + w] + aLv*local + aSv*g_ssm[base];
            g_xr[base] = xr;
            s[c*33 + j] = xr;
        }
    }
    __syncthreads();
    int w = tid >> 5, l = tid & 31;
    float v[6], sum = 0.f, sq = 0.f;
    #pragma unroll
    for (int i = 0; i < 6; i++) { v[i] = s[(l + 32*i)*33 + w]; sum += v[i]; sq += v[i]*v[i]; }
    #pragma unroll
    for (int o = 16; o > 0; o >>= 1) {
        sum += __shfl_xor_sync(0xffffffffu, sum, o);
        sq  += __shfl_xor_sync(0xffffffffu, sq,  o);
    }
    float mean = sum * (1.f/DIM), var = sq * (1.f/DIM) - mean*mean;
    float rs = rsqrtf(var + 1e-5f);
    float y[6];
    #pragma unroll
    for (int i = 0; i < 6; i++) { int c = l + 32*i; y[i] = (v[i] - mean) * rs * g1[c] + b1[c]; }
    __syncthreads();
    #pragma unroll
    for (int i = 0; i < 6; i++) s[(l + 32*i)*33 + w] = y[i];
    __syncthreads();
    #pragma unroll
    for (int i = 0; i < 6; i++) {
        int idx = tid + 1024*i;
        int tok = idx / 192, c = idx - tok*192;
        float val = s[c*33 + tok];
        if (MODE == 0) g_xn1[(size_t)(tok0 + tok)*DIM + c] = __float2half(val);
        else           g_xn3[(size_t)(tok0 + tok)*DIM + c] = __float2half(val);
    }
    if (MODE == 0) {
        float s2a = 0.f, s2b = 0.f;
        #pragma unroll
        for (int i = 0; i < 6; i++) { s2a += y[i]; s2b += y[i]*y[i]; }
        #pragma unroll
        for (int o = 16; o > 0; o >>= 1) {
            s2a += __shfl_xor_sync(0xffffffffu, s2a, o);
            s2b += __shfl_xor_sync(0xffffffffu, s2b, o);
        }
        float m2 = s2a * (1.f/DIM), v2 = s2b * (1.f/DIM) - m2*m2;
        float rs2 = rsqrtf(v2 + 1e-5f);
        __syncthreads();
        #pragma unroll
        for (int i = 0; i < 6; i++) { int c = l + 32*i; s[(l + 32*i)*33 + w] = (y[i] - m2) * rs2 * g2[c] + b2[c]; }
        __syncthreads();
        #pragma unroll
        for (int i = 0; i < 6; i++) {
            int idx = tid + 1024*i;
            int tok = idx / 192, c = idx - tok*192;
            g_xn2[(size_t)(tok0 + tok)*DIM + c] = __float2half(s[c*33 + tok]);
        }
    }
}

// ---------------- scan pass 1: elementwise + local chunk scans (stores h, Pcum) ----------------
__global__ void __launch_bounds__(256) k_scan1()
{
    int s = threadIdx.x;
    int bidx = blockIdx.x*4 + threadIdx.y;
    int b = bidx >> 9, ch = bidx & (NCH-1);
    float An = g_Aneg[s];
    float h = 0.f, P = 1.f;
    int tok0 = b*HWSZ + ch*CHL;
    bool c0 = (ch == 0);
    #pragma unroll
    for (int t = 0; t < CHL; t++) {
        const __half* p = g_proj + (size_t)(tok0 + t)*256;
        float dt = __half2float(p[s]);
        float Bv = __half2float(p[64+s]);
        float xv = __half2float(p[192+s]);
        float sp = fmaxf(dt, 0.f) + log1pf(expf(-fabsf(dt)));
        float delta = sp * 0.01f + 1e-4f;
        float dA = fminf(fmaxf(delta * An, -10.f), -1e-4f);
        float Av = fminf(fmaxf(expf(dA), 0.001f), 0.999f);
        float BX = delta * Bv * xv;
        h = (c0 && t == 0) ? BX : Av*(h + BX);
        P *= Av;
        size_t o = (size_t)(tok0 + t)*ST + s;
        g_h[o] = h;
        g_Pc[o] = P;
    }
    g_P[bidx*ST + s] = P;
    g_hend[bidx*ST + s] = h;
}

// ---------------- scan pass 2: warp-parallel affine scan over chunk carries ----------------
__global__ void __launch_bounds__(256) k_scan2()
{
    int gw = blockIdx.x*8 + (threadIdx.x >> 5);
    int lane = threadIdx.x & 31;
    int b = gw >> 6, s = gw & 63;
    int base = (b*NCH)*ST + s;

    float P[16], E[16];
    #pragma unroll
    for (int j = 0; j < 16; j++) {
        int ch = lane*16 + j;
        P[j] = g_P[base + ch*ST];
        E[j] = g_hend[base + ch*ST];
    }
    float tP = 1.f, tE = 0.f;
    #pragma unroll
    for (int j = 0; j < 16; j++) { float nP = P[j]*tP, nE = P[j]*tE + E[j]; tP = nP; tE = nE; }
    float sP = tP, sE = tE;
    #pragma unroll
    for (int off = 1; off < 32; off <<= 1) {
        float pP = __shfl_up_sync(0xffffffffu, sP, off);
        float pE = __shfl_up_sync(0xffffffffu, sE, off);
        if (lane >= off) { sE = sP*pE + sE; sP = sP*pP; }
    }
    float eP = __shfl_up_sync(0xffffffffu, sP, 1);
    float eE = __shfl_up_sync(0xffffffffu, sE, 1);
    if (lane == 0) { eP = 1.f; eE = 0.f; }
    float hP = eP, hE = eE;
    #pragma unroll
    for (int j = 0; j < 16; j++) {
        int ch = lane*16 + j;
        g_hin[base + ch*ST] = hE;
        float nP = P[j]*hP, nE = P[j]*hE + E[j];
        hP = nP; hE = nE;
    }
}

// ---------------- FP16 GEMM: 256 threads, 8 warps, warp tile 32x32, 3-stage ----------------
// EPI 0: A=g_xn2, B=g_wcat -> g_proj (half)
// EPI 2: A=g_xn3, B=g_w1 + gelu -> g_hid (half)
// EPI 3: A=g_hid, B=g_w2; out = g_xr + aM*v (NCHW float)
#define STAGEH ((128 + 64) * PITCHH)
template<int EPI, int N, int K>
__global__ void __launch_bounds__(256, 2) k_mma(const float* __restrict__ bias,
                                                const float* __restrict__ alpha,
                                                float* __restrict__ Cout)
{
    extern __shared__ char smc[];
    __half* stage0 = reinterpret_cast<__half*>(smc);
    const __half* A  = (EPI == 0) ? g_xn2 : (EPI == 2) ? g_xn3 : g_hid;
    const __half* Bp = (EPI == 0) ? g_wcat : (EPI == 2) ? g_w1 : g_w2;
    const float* bp = (EPI == 0) ? g_bias256 : bias;

    int tid = threadIdx.x;
    int wid = tid >> 5, lane = tid & 31;
    int g = lane >> 2, t4 = lane & 3;
    int row0 = blockIdx.y * 128, col0 = blockIdx.x * 64;
    int m0 = (wid & 3) * 32, n0 = (wid >> 2) * 32;
    int lrow = lane & 7, lmat = lane >> 3;
    int a_moff = (lmat & 1)*8, a_koff = (lmat >> 1)*8;
    int b_noff = (lmat >> 1)*8, b_koff = (lmat & 1)*8;

    float acc[2][4][4];
    #pragma unroll
    for (int mi = 0; mi < 2; mi++)
        #pragma unroll
        for (int ni = 0; ni < 4; ni++)
            #pragma unroll
            for (int e = 0; e < 4; e++) acc[mi][ni][e] = 0.f;

    const int NK = K / 64;
    auto load_slab = [&](int kt, int st) {
        __half* As = stage0 + st*STAGEH;
        __half* Bs = As + 128*PITCHH;
        int k0 = kt * 64;
        #pragma unroll
        for (int i = 0; i < 4; i++) {
            int idx = tid + 256*i;
            int m = idx >> 3, c = idx & 7;
            cp16(As + m*PITCHH + c*8, A + (size_t)(row0 + m)*K + k0 + c*8);
        }
        #pragma unroll
        for (int i = 0; i < 2; i++) {
            int idx = tid + 256*i;
            int n = idx >> 3, c = idx & 7;
            cp16(Bs + n*PITCHH + c*8, Bp + (size_t)(col0 + n)*K + k0 + c*8);
        }
    };
    load_slab(0, 0);
    cp_commit();
    if (NK > 1) { load_slab(1, 1); cp_commit(); }
    for (int kt = 0; kt < NK; kt++) {
        if (kt + 2 < NK) { load_slab(kt + 2, (kt + 2) % 3); cp_commit(); cp_wait<2>(); }
        else if (kt + 1 < NK) cp_wait<1>();
        else cp_wait<0>();
        __syncthreads();
        int cur = kt % 3;
        const __half* As = stage0 + cur*STAGEH;
        const __half* Bs = As + 128*PITCHH;
        #pragma unroll
        for (int ks = 0; ks < 4; ks++) {
            int kb = ks*16;
            uint32_t a[2][4], b[2][4];
            #pragma unroll
            for (int mi = 0; mi < 2; mi++)
                ldm4(a[mi], As + (m0 + mi*16 + lrow + a_moff)*PITCHH + kb + a_koff);
            #pragma unroll
            for (int nb = 0; nb < 2; nb++)
                ldm4(b[nb], Bs + (n0 + nb*16 + lrow + b_noff)*PITCHH + kb + b_koff);
            #pragma unroll
            for (int mi = 0; mi < 2; mi++)
                #pragma unroll
                for (int ni = 0; ni < 4; ni++)
                    mma_f16(acc[mi][ni], a[mi], &b[ni >> 1][(ni & 1)*2]);
        }
        __syncthreads();
    }

    if (EPI == 0 || EPI == 2) {
        #pragma unroll
        for (int mi = 0; mi < 2; mi++)
            #pragma unroll
            for (int ni = 0; ni < 4; ni++)
                #pragma unroll
                for (int e = 0; e < 4; e++) {
                    int m = row0 + m0 + mi*16 + g + ((e >> 1) << 3);
                    int n = col0 + n0 + ni*8 + t4*2 + (e & 1);
                    float v = acc[mi][ni][e] + bp[n];
                    if (EPI == 2) {
                        v = 0.5f * v * (1.f + erff(v * 0.7071067811865476f));
                        g_hid[(size_t)m*N + n] = __float2half(v);
                    } else {
                        g_proj[(size_t)m*N + n] = __float2half(v);
                    }
                }
    } else {
        float* T = reinterpret_cast<float*>(smc);
        __syncthreads();
        #pragma unroll
        for (int mi = 0; mi < 2; mi++)
            #pragma unroll
            for (int ni = 0; ni < 4; ni++)
                #pragma unroll
                for (int e = 0; e < 4; e++) {
                    int ml = m0 + mi*16 + g + ((e >> 1) << 3);
                    int nl = n0 + ni*8 + t4*2 + (e & 1);
                    T[nl*129 + ml] = acc[mi][ni][e] + bp[col0 + nl];
                }
        __syncthreads();
        int bb = row0 >> 12, hw0 = row0 & (HWSZ-1);
        float av = alpha[0];
        #pragma unroll
        for (int i = 0; i < 32; i++) {
            int idx = tid + 256*i;
            int nl = idx >> 7, ml = idx & 127;
            size_t adr = ((size_t)(bb*DIM + col0 + nl))*HWSZ + hw0 + ml;
            Cout[adr] = g_xr[adr] + av * T[nl*129 + ml];
        }
    }
}

// ---------------- EPI1 GEMM with fused scan fix-up (K=64, single slab) ----------------
// A[m][s] = C[m][s] * (h[m][s] + Pc[m][s]*hin[chunk(m)][s]);  C = proj[:,128:192]
// D-term + NCHW writeout to g_ssm.
__global__ void __launch_bounds__(256, 2) k_mma1(const float* __restrict__ bias,
                                                 const float* __restrict__ Dp)
{
    extern __shared__ char smc[];
    __half* As = reinterpret_cast<__half*>(smc);
    __half* Bs = As + 128*PITCHH;
    int tid = threadIdx.x;
    int wid = tid >> 5, lane = tid & 31;
    int g = lane >> 2, t4 = lane & 3;
    int row0 = blockIdx.y * 128, col0 = blockIdx.x * 64;
    int m0 = (wid & 3) * 32, n0 = (wid >> 2) * 32;
    int lrow = lane & 7, lmat = lane >> 3;
    int a_moff = (lmat & 1)*8, a_koff = (lmat >> 1)*8;
    int b_noff = (lmat >> 1)*8, b_koff = (lmat & 1)*8;

    // B (out_w) via cp.async
    #pragma unroll
    for (int i = 0; i < 2; i++) {
        int idx = tid + 256*i;
        int n = idx >> 3, c = idx & 7;
        cp16(Bs + n*PITCHH + c*8, g_wout + (size_t)(col0 + n)*ST + c*8);
    }
    cp_commit();

    // A fused construct: yh = C * (h + Pc*hin)
    int bb = row0 >> 12;
    int chbase = (row0 & (HWSZ-1)) >> 3;   // chunk of first row (CHL=8)
    #pragma unroll
    for (int i = 0; i < 4; i++) {
        int idx = tid + 256*i;
        int m = idx >> 3, s0 = (idx & 7)*8;
        int tok = row0 + m;
        size_t o = (size_t)tok*ST + s0;
        float4 h0 = *reinterpret_cast<const float4*>(g_h + o);
        float4 h1 = *reinterpret_cast<const float4*>(g_h + o + 4);
        float4 p0 = *reinterpret_cast<const float4*>(g_Pc + o);
        float4 p1 = *reinterpret_cast<const float4*>(g_Pc + o + 4);
        int bidx = bb*NCH + chbase + (m >> 3);
        const float* hp = g_hin + (size_t)bidx*ST + s0;
        float4 i0 = *reinterpret_cast<const float4*>(hp);
        float4 i1 = *reinterpret_cast<const float4*>(hp + 4);
        const __half* cp_ = g_proj + (size_t)tok*256 + 128 + s0;
        uint4 cu = *reinterpret_cast<const uint4*>(cp_);
        const __half* ch8 = reinterpret_cast<const __half*>(&cu);
        float hf[8];
        hf[0] = h0.x + p0.x*i0.x; hf[1] = h0.y + p0.y*i0.y;
        hf[2] = h0.z + p0.z*i0.z; hf[3] = h0.w + p0.w*i0.w;
        hf[4] = h1.x + p1.x*i1.x; hf[5] = h1.y + p1.y*i1.y;
        hf[6] = h1.z + p1.z*i1.z; hf[7] = h1.w + p1.w*i1.w;
        __half out8[8];
        #pragma unroll
        for (int j = 0; j < 8; j++)
            out8[j] = __float2half(__half2float(ch8[j]) * hf[j]);
        *reinterpret_cast<uint4*>(As + m*PITCHH + s0) = *reinterpret_cast<uint4*>(out8);
    }
    cp_wait<0>();
    __syncthreads();

    float acc[2][4][4];
    #pragma unroll
    for (int mi = 0; mi < 2; mi++)
        #pragma unroll
        for (int ni = 0; ni < 4; ni++)
            #pragma unroll
            for (int e = 0; e < 4; e++) acc[mi][ni][e] = 0.f;

    #pragma unroll
    for (int ks = 0; ks < 4; ks++) {
        int kb = ks*16;
        uint32_t a[2][4], b[2][4];
        #pragma unroll
        for (int mi = 0; mi < 2; mi++)
            ldm4(a[mi], As + (m0 + mi*16 + lrow + a_moff)*PITCHH + kb + a_koff);
        #pragma unroll
        for (int nb = 0; nb < 2; nb++)
            ldm4(b[nb], Bs + (n0 + nb*16 + lrow + b_noff)*PITCHH + kb + b_koff);
        #pragma unroll
        for (int mi = 0; mi < 2; mi++)
            #pragma unroll
            for (int ni = 0; ni < 4; ni++)
                mma_f16(acc[mi][ni], a[mi], &b[ni >> 1][(ni & 1)*2]);
    }
    __syncthreads();

    // epilogue: bias + D*xn1, smem transpose, NCHW write to g_ssm
    float* T = reinterpret_cast<float*>(smc);
    #pragma unroll
    for (int mi = 0; mi < 2; mi++)
        #pragma unroll
        for (int ni = 0; ni < 4; ni++)
            #pragma unroll
            for (int e = 0; e < 4; e++) {
                int ml = m0 + mi*16 + g + ((e >> 1) << 3);
                int nl = n0 + ni*8 + t4*2 + (e & 1);
                int n = col0 + nl;
                float v = acc[mi][ni][e] + bias[n];
                float d = fminf(fmaxf(Dp[n], -2.f), 2.f);
                v += d * __half2float(g_xn1[(size_t)(row0 + ml)*DIM + n]);
                T[nl*129 + ml] = v;
            }
    __syncthreads();
    int hw0 = row0 & (HWSZ-1);
    #pragma unroll
    for (int i = 0; i < 32; i++) {
        int idx = tid + 256*i;
        int nl = idx >> 7, ml = idx & 127;
        g_ssm[((size_t)(bb*DIM + col0 + nl))*HWSZ + hw0 + ml] = T[nl*129 + ml];
    }
}

// smem sizes
#define SMEM_MAIN (3*STAGEH*2)          // 82944 B
#define SMEM_TRANS (64*129*4)           // 33024 B
#define SMEM_K (SMEM_MAIN > SMEM_TRANS ? SMEM_MAIN : SMEM_TRANS)
#define SMEM_M1 (((128+64)*PITCHH*2) > SMEM_TRANS ? ((128+64)*PITCHH*2) : SMEM_TRANS)

// ---------------- launch ----------------
extern "C" void kernel_launch(void* const* d_in, const int* in_sizes, int n_in,
                              void* d_out, int out_size)
{
    const float* x        = (const float*)d_in[0];
    const float* ln1_g    = (const float*)d_in[1];
    const float* ln1_b    = (const float*)d_in[2];
    const float* ln2_g    = (const float*)d_in[3];
    const float* ln2_b    = (const float*)d_in[4];
    const float* dw_w     = (const float*)d_in[5];
    const float* bn_g     = (const float*)d_in[6];
    const float* bn_b     = (const float*)d_in[7];
    const float* bn_rm    = (const float*)d_in[8];
    const float* bn_rv    = (const float*)d_in[9];
    const float* ssm_ln_g = (const float*)d_in[10];
    const float* ssm_ln_b = (const float*)d_in[11];
    const float* xp_w     = (const float*)d_in[12];
    const float* xp_b     = (const float*)d_in[13];
    const float* dt_w     = (const float*)d_in[14];
    const float* dt_b     = (const float*)d_in[15];
    const float* A_log    = (const float*)d_in[16];
    const float* B_w      = (const float*)d_in[17];
    const float* C_w      = (const float*)d_in[18];
    const float* D_param  = (const float*)d_in[19];
    const float* out_w    = (const float*)d_in[20];
    const float* out_b    = (const float*)d_in[21];
    const float* mlp_w1   = (const float*)d_in[22];
    const float* mlp_b1   = (const float*)d_in[23];
    const float* mlp_w2   = (const float*)d_in[24];
    const float* mlp_b2   = (const float*)d_in[25];
    const float* aL       = (const float*)d_in[26];
    const float* aS       = (const float*)d_in[27];
    const float* aM       = (const float*)d_in[28];
    float* out = (float*)d_out;

    cudaFuncSetAttribute(k_mma<0,256,192>, cudaFuncAttributeMaxDynamicSharedMemorySize, SMEM_K);
    cudaFuncSetAttribute(k_mma<2,HID,192>, cudaFuncAttributeMaxDynamicSharedMemorySize, SMEM_K);
    cudaFuncSetAttribute(k_mma<3,192,HID>, cudaFuncAttributeMaxDynamicSharedMemorySize, SMEM_K);
    cudaFuncSetAttribute(k_mma1, cudaFuncAttributeMaxDynamicSharedMemorySize, SMEM_M1);

    k_prep<<<576, 256>>>(dt_w, B_w, C_w, xp_w, dt_b, xp_b, A_log, out_w, mlp_w1, mlp_w2);
    k_ln<0><<<TOK/32, 1024>>>(x, ln1_g, ln1_b, ssm_ln_g, ssm_ln_b,
                              nullptr, nullptr, nullptr, nullptr, nullptr, nullptr, nullptr);
    k_mma<0, 256, 192><<<dim3(4, TOK/128), 256, SMEM_K>>>(nullptr, nullptr, nullptr);
    k_scan1<<<NB*NCH/4, dim3(64,4)>>>();
    k_scan2<<<64, 256>>>();
    k_mma1<<<dim3(3, TOK/128), 256, SMEM_M1>>>(out_b, D_param);
    k_ln<1><<<TOK/32, 1024>>>(x, ln2_g, ln2_b, nullptr, nullptr,
                              dw_w, bn_g, bn_b, bn_rm, bn_rv, aL, aS);
    k_mma<2, HID, 192><<<dim3(12, TOK/128), 256, SMEM_K>>>(mlp_b1, nullptr, nullptr);
    k_mma<3, 192, HID><<<dim3(3, TOK/128), 256, SMEM_K>>>(mlp_b2, aM, out);
}

// round 17
// speedup vs baseline: 1.0969x; 1.0125x over previous
#include <cuda_runtime.h>
#include <cuda_fp16.h>
#include <math.h>
#include <stdint.h>

#define NB   8
#define DIM  192
#define ST   64
#define HWSZ 4096
#define TOK  (NB*HWSZ)
#define HID  768
#define CHL  8
#define NCH  (HWSZ/CHL)     // 512
#define PITCHH 72           // smem row pitch in halfs (144B) -> conflict-free ldmatrix

// ---------------- scratch ----------------
__device__ __align__(16) __half g_xn1[TOK*DIM];
__device__ __align__(16) __half g_xn2[TOK*DIM];
__device__ __align__(16) __half g_proj[TOK*256];
__device__ __align__(16) float g_Pc[TOK*ST];
__device__ __align__(16) float g_h[TOK*ST];
__device__ float g_ssm[(size_t)TOK*DIM];
__device__ float g_xr[(size_t)TOK*DIM];
__device__ __align__(16) __half g_xn3[TOK*DIM];
__device__ __align__(16) __half g_hid[(size_t)TOK*HID];
__device__ __align__(16) __half g_wcat[256*DIM];
__device__ __align__(16) __half g_wout[DIM*ST];
__device__ __align__(16) __half g_w1[HID*DIM];
__device__ __align__(16) __half g_w2[DIM*HID];
__device__ float g_bias256[256];
__device__ float g_Aneg[ST];
__device__ float g_P[NB*NCH*ST];
__device__ float g_hend[NB*NCH*ST];
__device__ __align__(16) float g_hin[NB*NCH*ST];

// ---------------- helpers ----------------
__device__ __forceinline__ void cp16(void* dst_smem, const void* src)
{
    uint32_t d = (uint32_t)__cvta_generic_to_shared(dst_smem);
    asm volatile("cp.async.cg.shared.global [%0], [%1], 16;" :: "r"(d), "l"(src));
}
__device__ __forceinline__ void cp_commit() { asm volatile("cp.async.commit_group;"); }
template<int W> __device__ __forceinline__ void cp_wait() { asm volatile("cp.async.wait_group %0;" :: "n"(W)); }

__device__ __forceinline__ void ldm4(uint32_t* r, const void* smem)
{
    uint32_t a = (uint32_t)__cvta_generic_to_shared(smem);
    asm volatile("ldmatrix.sync.aligned.m8n8.x4.shared.b16 {%0,%1,%2,%3}, [%4];"
                 : "=r"(r[0]), "=r"(r[1]), "=r"(r[2]), "=r"(r[3]) : "r"(a));
}
__device__ __forceinline__ void mma_f16(float* c, const uint32_t* a, const uint32_t* b)
{
    asm volatile("mma.sync.aligned.m16n8k16.row.col.f32.f16.f16.f32 "
        "{%0,%1,%2,%3}, {%4,%5,%6,%7}, {%8,%9}, {%0,%1,%2,%3};"
        : "+f"(c[0]), "+f"(c[1]), "+f"(c[2]), "+f"(c[3])
        : "r"(a[0]), "r"(a[1]), "r"(a[2]), "r"(a[3]), "r"(b[0]), "r"(b[1]));
}

// ---------------- prep ----------------
__global__ void k_prep(const float* __restrict__ dt_w, const float* __restrict__ B_w,
                       const float* __restrict__ C_w,  const float* __restrict__ xp_w,
                       const float* __restrict__ dt_b, const float* __restrict__ xp_b,
                       const float* __restrict__ A_log, const float* __restrict__ out_w,
                       const float* __restrict__ mlp_w1, const float* __restrict__ mlp_w2)
{
    int i = blockIdx.x * blockDim.x + threadIdx.x;
    if (i < 256*DIM) {
        int n = i / DIM, k = i - n*DIM;
        float v;
        if      (n < 64)  v = dt_w[n*DIM + k];
        else if (n < 128) v = B_w[(n-64)*DIM + k];
        else if (n < 192) v = C_w[(n-128)*DIM + k];
        else              v = xp_w[(n-192)*DIM + k];
        g_wcat[i] = __float2half(v);
    }
    if (i < DIM*ST)  g_wout[i] = __float2half(out_w[i]);
    if (i < HID*DIM) { g_w1[i] = __float2half(mlp_w1[i]); g_w2[i] = __float2half(mlp_w2[i]); }
    if (i < 256) {
        float b = 0.f;
        if (i < 64)        b = dt_b[i];
        else if (i >= 192) b = xp_b[i-192];
        g_bias256[i] = b;
    }
    if (i < ST) g_Aneg[i] = -expf(A_log[i]);
}

// ---------------- LayerNorm (coalesced, 32 tok/block) ----------------
template<int MODE>
__global__ void __launch_bounds__(1024) k_ln(const float* __restrict__ xin,
                     const float* __restrict__ g1, const float* __restrict__ b1,
                     const float* __restrict__ g2, const float* __restrict__ b2,
                     const float* __restrict__ dw,
                     const float* __restrict__ bn_g, const float* __restrict__ bn_b,
                     const float* __restrict__ bn_rm, const float* __restrict__ bn_rv,
                     const float* __restrict__ aL, const float* __restrict__ aS)
{
    __shared__ float s[192*33];
    int tid = threadIdx.x;
    int tok0 = blockIdx.x * 32;
    int b = tok0 >> 12, hw0 = tok0 & (HWSZ-1);

    if (MODE == 0) {
        #pragma unroll
        for (int i = 0; i < 6; i++) {
            int idx = tid + 1024*i;
            int c = idx >> 5, j = idx & 31;
            s[c*33 + j] = xin[((size_t)(b*DIM + c))*HWSZ + hw0 + j];
        }
    } else {
        int h = hw0 >> 6, w0 = hw0 & 63;
        float aLv = aL[0], aSv = aS[0];
        #pragma unroll
        for (int i = 0; i < 6; i++) {
            int idx = tid + 1024*i;
            int c = idx >> 5, j = idx & 31;
            int w = w0 + j;
            const float* xb = xin + ((size_t)(b*DIM + c))*HWSZ;
            const float* wk = dw + c*9;
            float acc = 0.f;
            #pragma unroll
            for (int kh = 0; kh < 3; kh++) {
                int hh = h + kh - 1;
                if (hh < 0 || hh >= 64) continue;
                #pragma unroll
                for (int kw = 0; kw < 3; kw++) {
                    int ww = w + kw - 1;
                    if (ww < 0 || ww >= 64) continue;
                    acc += xb[hh*64 + ww] * wk[kh*3 + kw];
                }
            }
            float scale = bn_g[c] * rsqrtf(bn_rv[c] + 1e-5f);
            float local = (acc - bn_rm[c]) * scale + bn_b[c];
            size_t base = ((size_t)(b*DIM + c))*HWSZ + h*64 + w;
            float xr = xb[h*64 + w] + aLv*local + aSv*g_ssm[base];
            g_xr[base] = xr;
            s[c*33 + j] = xr;
        }
    }
    __syncthreads();
    int w = tid >> 5, l = tid & 31;
    float v[6], sum = 0.f, sq = 0.f;
    #pragma unroll
    for (int i = 0; i < 6; i++) { v[i] = s[(l + 32*i)*33 + w]; sum += v[i]; sq += v[i]*v[i]; }
    #pragma unroll
    for (int o = 16; o > 0; o >>= 1) {
        sum += __shfl_xor_sync(0xffffffffu, sum, o);
        sq  += __shfl_xor_sync(0xffffffffu, sq,  o);
    }
    float mean = sum * (1.f/DIM), var = sq * (1.f/DIM) - mean*mean;
    float rs = rsqrtf(var + 1e-5f);
    float y[6];
    #pragma unroll
    for (int i = 0; i < 6; i++) { int c = l + 32*i; y[i] = (v[i] - mean) * rs * g1[c] + b1[c]; }
    __syncthreads();
    #pragma unroll
    for (int i = 0; i < 6; i++) s[(l + 32*i)*33 + w] = y[i];
    __syncthreads();
    #pragma unroll
    for (int i = 0; i < 6; i++) {
        int idx = tid + 1024*i;
        int tok = idx / 192, c = idx - tok*192;
        float val = s[c*33 + tok];
        if (MODE == 0) g_xn1[(size_t)(tok0 + tok)*DIM + c] = __float2half(val);
        else           g_xn3[(size_t)(tok0 + tok)*DIM + c] = __float2half(val);
    }
    if (MODE == 0) {
        float s2a = 0.f, s2b = 0.f;
        #pragma unroll
        for (int i = 0; i < 6; i++) { s2a += y[i]; s2b += y[i]*y[i]; }
        #pragma unroll
        for (int o = 16; o > 0; o >>= 1) {
            s2a += __shfl_xor_sync(0xffffffffu, s2a, o);
            s2b += __shfl_xor_sync(0xffffffffu, s2b, o);
        }
        float m2 = s2a * (1.f/DIM), v2 = s2b * (1.f/DIM) - m2*m2;
        float rs2 = rsqrtf(v2 + 1e-5f);
        __syncthreads();
        #pragma unroll
        for (int i = 0; i < 6; i++) { int c = l + 32*i; s[(l + 32*i)*33 + w] = (y[i] - m2) * rs2 * g2[c] + b2[c]; }
        __syncthreads();
        #pragma unroll
        for (int i = 0; i < 6; i++) {
            int idx = tid + 1024*i;
            int tok = idx / 192, c = idx - tok*192;
            g_xn2[(size_t)(tok0 + tok)*DIM + c] = __float2half(s[c*33 + tok]);
        }
    }
}

// ---------------- scan pass 1: elementwise + local chunk scans (stores h, Pcum) ----------------
__global__ void __launch_bounds__(256) k_scan1()
{
    int s = threadIdx.x;
    int bidx = blockIdx.x*4 + threadIdx.y;
    int b = bidx >> 9, ch = bidx & (NCH-1);
    float An = g_Aneg[s];
    float h = 0.f, P = 1.f;
    int tok0 = b*HWSZ + ch*CHL;
    bool c0 = (ch == 0);
    #pragma unroll
    for (int t = 0; t < CHL; t++) {
        const __half* p = g_proj + (size_t)(tok0 + t)*256;
        float dt = __half2float(p[s]);
        float Bv = __half2float(p[64+s]);
        float xv = __half2float(p[192+s]);
        float sp = fmaxf(dt, 0.f) + log1pf(expf(-fabsf(dt)));
        float delta = sp * 0.01f + 1e-4f;
        float dA = fminf(fmaxf(delta * An, -10.f), -1e-4f);
        float Av = fminf(fmaxf(expf(dA), 0.001f), 0.999f);
        float BX = delta * Bv * xv;
        h = (c0 && t == 0) ? BX : Av*(h + BX);
        P *= Av;
        size_t o = (size_t)(tok0 + t)*ST + s;
        g_h[o] = h;
        g_Pc[o] = P;
    }
    g_P[bidx*ST + s] = P;
    g_hend[bidx*ST + s] = h;
}

// ---------------- scan pass 2: warp-parallel affine scan over chunk carries ----------------
__global__ void __launch_bounds__(256) k_scan2()
{
    int gw = blockIdx.x*8 + (threadIdx.x >> 5);
    int lane = threadIdx.x & 31;
    int b = gw >> 6, s = gw & 63;
    int base = (b*NCH)*ST + s;

    float P[16], E[16];
    #pragma unroll
    for (int j = 0; j < 16; j++) {
        int ch = lane*16 + j;
        P[j] = g_P[base + ch*ST];
        E[j] = g_hend[base + ch*ST];
    }
    float tP = 1.f, tE = 0.f;
    #pragma unroll
    for (int j = 0; j < 16; j++) { float nP = P[j]*tP, nE = P[j]*tE + E[j]; tP = nP; tE = nE; }
    float sP = tP, sE = tE;
    #pragma unroll
    for (int off = 1; off < 32; off <<= 1) {
        float pP = __shfl_up_sync(0xffffffffu, sP, off);
        float pE = __shfl_up_sync(0xffffffffu, sE, off);
        if (lane >= off) { sE = sP*pE + sE; sP = sP*pP; }
    }
    float eP = __shfl_up_sync(0xffffffffu, sP, 1);
    float eE = __shfl_up_sync(0xffffffffu, sE, 1);
    if (lane == 0) { eP = 1.f; eE = 0.f; }
    float hP = eP, hE = eE;
    #pragma unroll
    for (int j = 0; j < 16; j++) {
        int ch = lane*16 + j;
        g_hin[base + ch*ST] = hE;
        float nP = P[j]*hP, nE = P[j]*hE + E[j];
        hP = nP; hE = nE;
    }
}

// ---------------- FP16 GEMM: 256 threads, 8 warps, warp tile 32x32, 3-stage, 1 sync/slab ----------------
// EPI 0: A=g_xn2, B=g_wcat -> g_proj (half)
// EPI 2: A=g_xn3, B=g_w1 + gelu -> g_hid (half)
// EPI 3: A=g_hid, B=g_w2; out = g_xr + aM*v (NCHW float)
#define STAGEH ((128 + 64) * PITCHH)
template<int EPI, int N, int K>
__global__ void __launch_bounds__(256, 2) k_mma(const float* __restrict__ bias,
                                                const float* __restrict__ alpha,
                                                float* __restrict__ Cout)
{
    extern __shared__ char smc[];
    __half* stage0 = reinterpret_cast<__half*>(smc);
    const __half* A  = (EPI == 0) ? g_xn2 : (EPI == 2) ? g_xn3 : g_hid;
    const __half* Bp = (EPI == 0) ? g_wcat : (EPI == 2) ? g_w1 : g_w2;
    const float* bp = (EPI == 0) ? g_bias256 : bias;

    int tid = threadIdx.x;
    int wid = tid >> 5, lane = tid & 31;
    int g = lane >> 2, t4 = lane & 3;
    int row0 = blockIdx.y * 128, col0 = blockIdx.x * 64;
    int m0 = (wid & 3) * 32, n0 = (wid >> 2) * 32;
    int lrow = lane & 7, lmat = lane >> 3;
    int a_moff = (lmat & 1)*8, a_koff = (lmat >> 1)*8;
    int b_noff = (lmat >> 1)*8, b_koff = (lmat & 1)*8;

    float acc[2][4][4];
    #pragma unroll
    for (int mi = 0; mi < 2; mi++)
        #pragma unroll
        for (int ni = 0; ni < 4; ni++)
            #pragma unroll
            for (int e = 0; e < 4; e++) acc[mi][ni][e] = 0.f;

    const int NK = K / 64;
    auto load_slab = [&](int kt, int st) {
        __half* As = stage0 + st*STAGEH;
        __half* Bs = As + 128*PITCHH;
        int k0 = kt * 64;
        #pragma unroll
        for (int i = 0; i < 4; i++) {
            int idx = tid + 256*i;
            int m = idx >> 3, c = idx & 7;
            cp16(As + m*PITCHH + c*8, A + (size_t)(row0 + m)*K + k0 + c*8);
        }
        #pragma unroll
        for (int i = 0; i < 2; i++) {
            int idx = tid + 256*i;
            int n = idx >> 3, c = idx & 7;
            cp16(Bs + n*PITCHH + c*8, Bp + (size_t)(col0 + n)*K + k0 + c*8);
        }
    };
    load_slab(0, 0);
    cp_commit();
    if (NK > 1) { load_slab(1, 1); cp_commit(); }
    for (int kt = 0; kt < NK; kt++) {
        // wait for slab kt; at this point committed groups are 0..min(kt+1,NK-1)
        if (kt + 1 < NK) cp_wait<1>();
        else cp_wait<0>();
        __syncthreads();                 // all warps done with compute(kt-1); stage (kt+2)%3 free
        if (kt + 2 < NK) { load_slab(kt + 2, (kt + 2) % 3); cp_commit(); }
        int cur = kt % 3;
        const __half* As = stage0 + cur*STAGEH;
        const __half* Bs = As + 128*PITCHH;
        #pragma unroll
        for (int ks = 0; ks < 4; ks++) {
            int kb = ks*16;
            uint32_t a[2][4], b[2][4];
            #pragma unroll
            for (int mi = 0; mi < 2; mi++)
                ldm4(a[mi], As + (m0 + mi*16 + lrow + a_moff)*PITCHH + kb + a_koff);
            #pragma unroll
            for (int nb = 0; nb < 2; nb++)
                ldm4(b[nb], Bs + (n0 + nb*16 + lrow + b_noff)*PITCHH + kb + b_koff);
            #pragma unroll
            for (int mi = 0; mi < 2; mi++)
                #pragma unroll
                for (int ni = 0; ni < 4; ni++)
                    mma_f16(acc[mi][ni], a[mi], &b[ni >> 1][(ni & 1)*2]);
        }
    }
    __syncthreads();

    if (EPI == 0 || EPI == 2) {
        #pragma unroll
        for (int mi = 0; mi < 2; mi++)
            #pragma unroll
            for (int ni = 0; ni < 4; ni++)
                #pragma unroll
                for (int e = 0; e < 4; e++) {
                    int m = row0 + m0 + mi*16 + g + ((e >> 1) << 3);
                    int n = col0 + n0 + ni*8 + t4*2 + (e & 1);
                    float v = acc[mi][ni][e] + bp[n];
                    if (EPI == 2) {
                        v = 0.5f * v * (1.f + erff(v * 0.7071067811865476f));
                        g_hid[(size_t)m*N + n] = __float2half(v);
                    } else {
                        g_proj[(size_t)m*N + n] = __float2half(v);
                    }
                }
    } else {
        float* T = reinterpret_cast<float*>(smc);
        #pragma unroll
        for (int mi = 0; mi < 2; mi++)
            #pragma unroll
            for (int ni = 0; ni < 4; ni++)
                #pragma unroll
                for (int e = 0; e < 4; e++) {
                    int ml = m0 + mi*16 + g + ((e >> 1) << 3);
                    int nl = n0 + ni*8 + t4*2 + (e & 1);
                    T[nl*129 + ml] = acc[mi][ni][e] + bp[col0 + nl];
                }
        __syncthreads();
        int bb = row0 >> 12, hw0 = row0 & (HWSZ-1);
        float av = alpha[0];
        #pragma unroll
        for (int i = 0; i < 32; i++) {
            int idx = tid + 256*i;
            int nl = idx >> 7, ml = idx & 127;
            size_t adr = ((size_t)(bb*DIM + col0 + nl))*HWSZ + hw0 + ml;
            Cout[adr] = g_xr[adr] + av * T[nl*129 + ml];
        }
    }
}

// ---------------- EPI1 GEMM with fused scan fix-up (K=64, single slab) ----------------
__global__ void __launch_bounds__(256, 2) k_mma1(const float* __restrict__ bias,
                                                 const float* __restrict__ Dp)
{
    extern __shared__ char smc[];
    __half* As = reinterpret_cast<__half*>(smc);
    __half* Bs = As + 128*PITCHH;
    int tid = threadIdx.x;
    int wid = tid >> 5, lane = tid & 31;
    int g = lane >> 2, t4 = lane & 3;
    int row0 = blockIdx.y * 128, col0 = blockIdx.x * 64;
    int m0 = (wid & 3) * 32, n0 = (wid >> 2) * 32;
    int lrow = lane & 7, lmat = lane >> 3;
    int a_moff = (lmat & 1)*8, a_koff = (lmat >> 1)*8;
    int b_noff = (lmat >> 1)*8, b_koff = (lmat & 1)*8;

    #pragma unroll
    for (int i = 0; i < 2; i++) {
        int idx = tid + 256*i;
        int n = idx >> 3, c = idx & 7;
        cp16(Bs + n*PITCHH + c*8, g_wout + (size_t)(col0 + n)*ST + c*8);
    }
    cp_commit();

    int bb = row0 >> 12;
    int chbase = (row0 & (HWSZ-1)) >> 3;
    #pragma unroll
    for (int i = 0; i < 4; i++) {
        int idx = tid + 256*i;
        int m = idx >> 3, s0 = (idx & 7)*8;
        int tok = row0 + m;
        size_t o = (size_t)tok*ST + s0;
        float4 h0 = *reinterpret_cast<const float4*>(g_h + o);
        float4 h1 = *reinterpret_cast<const float4*>(g_h + o + 4);
        float4 p0 = *reinterpret_cast<const float4*>(g_Pc + o);
        float4 p1 = *reinterpret_cast<const float4*>(g_Pc + o + 4);
        int bidx = bb*NCH + chbase + (m >> 3);
        const float* hp = g_hin + (size_t)bidx*ST + s0;
        float4 i0 = *reinterpret_cast<const float4*>(hp);
        float4 i1 = *reinterpret_cast<const float4*>(hp + 4);
        const __half* cp_ = g_proj + (size_t)tok*256 + 128 + s0;
        uint4 cu = *reinterpret_cast<const uint4*>(cp_);
        const __half* ch8 = reinterpret_cast<const __half*>(&cu);
        float hf[8];
        hf[0] = h0.x + p0.x*i0.x; hf[1] = h0.y + p0.y*i0.y;
        hf[2] = h0.z + p0.z*i0.z; hf[3] = h0.w + p0.w*i0.w;
        hf[4] = h1.x + p1.x*i1.x; hf[5] = h1.y + p1.y*i1.y;
        hf[6] = h1.z + p1.z*i1.z; hf[7] = h1.w + p1.w*i1.w;
        __half out8[8];
        #pragma unroll
        for (int j = 0; j < 8; j++)
            out8[j] = __float2half(__half2float(ch8[j]) * hf[j]);
        *reinterpret_cast<uint4*>(As + m*PITCHH + s0) = *reinterpret_cast<uint4*>(out8);
    }
    cp_wait<0>();
    __syncthreads();

    float acc[2][4][4];
    #pragma unroll
    for (int mi = 0; mi < 2; mi++)
        #pragma unroll
        for (int ni = 0; ni < 4; ni++)
            #pragma unroll
            for (int e = 0; e < 4; e++) acc[mi][ni][e] = 0.f;

    #pragma unroll
    for (int ks = 0; ks < 4; ks++) {
        int kb = ks*16;
        uint32_t a[2][4], b[2][4];
        #pragma unroll
        for (int mi = 0; mi < 2; mi++)
            ldm4(a[mi], As + (m0 + mi*16 + lrow + a_moff)*PITCHH + kb + a_koff);
        #pragma unroll
        for (int nb = 0; nb < 2; nb++)
            ldm4(b[nb], Bs + (n0 + nb*16 + lrow + b_noff)*PITCHH + kb + b_koff);
        #pragma unroll
        for (int mi = 0; mi < 2; mi++)
            #pragma unroll
            for (int ni = 0; ni < 4; ni++)
                mma_f16(acc[mi][ni], a[mi], &b[ni >> 1][(ni & 1)*2]);
    }
    __syncthreads();

    float* T = reinterpret_cast<float*>(smc);
    #pragma unroll
    for (int mi = 0; mi < 2; mi++)
        #pragma unroll
        for (int ni = 0; ni < 4; ni++)
            #pragma unroll
            for (int e = 0; e < 4; e++) {
                int ml = m0 + mi*16 + g + ((e >> 1) << 3);
                int nl = n0 + ni*8 + t4*2 + (e & 1);
                int n = col0 + nl;
                float v = acc[mi][ni][e] + bias[n];
                float d = fminf(fmaxf(Dp[n], -2.f), 2.f);
                v += d * __half2float(g_xn1[(size_t)(row0 + ml)*DIM + n]);
                T[nl*129 + ml] = v;
            }
    __syncthreads();
    int hw0 = row0 & (HWSZ-1);
    #pragma unroll
    for (int i = 0; i < 32; i++) {
        int idx = tid + 256*i;
        int nl = idx >> 7, ml = idx & 127;
        g_ssm[((size_t)(bb*DIM + col0 + nl))*HWSZ + hw0 + ml] = T[nl*129 + ml];
    }
}

// smem sizes
#define SMEM_MAIN (3*STAGEH*2)          // 82944 B
#define SMEM_TRANS (64*129*4)           // 33024 B
#define SMEM_K (SMEM_MAIN > SMEM_TRANS ? SMEM_MAIN : SMEM_TRANS)
#define SMEM_M1 (((128+64)*PITCHH*2) > SMEM_TRANS ? ((128+64)*PITCHH*2) : SMEM_TRANS)

// ---------------- launch ----------------
extern "C" void kernel_launch(void* const* d_in, const int* in_sizes, int n_in,
                              void* d_out, int out_size)
{
    const float* x        = (const float*)d_in[0];
    const float* ln1_g    = (const float*)d_in[1];
    const float* ln1_b    = (const float*)d_in[2];
    const float* ln2_g    = (const float*)d_in[3];
    const float* ln2_b    = (const float*)d_in[4];
    const float* dw_w     = (const float*)d_in[5];
    const float* bn_g     = (const float*)d_in[6];
    const float* bn_b     = (const float*)d_in[7];
    const float* bn_rm    = (const float*)d_in[8];
    const float* bn_rv    = (const float*)d_in[9];
    const float* ssm_ln_g = (const float*)d_in[10];
    const float* ssm_ln_b = (const float*)d_in[11];
    const float* xp_w     = (const float*)d_in[12];
    const float* xp_b     = (const float*)d_in[13];
    const float* dt_w     = (const float*)d_in[14];
    const float* dt_b     = (const float*)d_in[15];
    const float* A_log    = (const float*)d_in[16];
    const float* B_w      = (const float*)d_in[17];
    const float* C_w      = (const float*)d_in[18];
    const float* D_param  = (const float*)d_in[19];
    const float* out_w    = (const float*)d_in[20];
    const float* out_b    = (const float*)d_in[21];
    const float* mlp_w1   = (const float*)d_in[22];
    const float* mlp_b1   = (const float*)d_in[23];
    const float* mlp_w2   = (const float*)d_in[24];
    const float* mlp_b2   = (const float*)d_in[25];
    const float* aL       = (const float*)d_in[26];
    const float* aS       = (const float*)d_in[27];
    const float* aM       = (const float*)d_in[28];
    float* out = (float*)d_out;

    cudaFuncSetAttribute(k_mma<0,256,192>, cudaFuncAttributeMaxDynamicSharedMemorySize, SMEM_K);
    cudaFuncSetAttribute(k_mma<2,HID,192>, cudaFuncAttributeMaxDynamicSharedMemorySize, SMEM_K);
    cudaFuncSetAttribute(k_mma<3,192,HID>, cudaFuncAttributeMaxDynamicSharedMemorySize, SMEM_K);
    cudaFuncSetAttribute(k_mma1, cudaFuncAttributeMaxDynamicSharedMemorySize, SMEM_M1);

    k_prep<<<576, 256>>>(dt_w, B_w, C_w, xp_w, dt_b, xp_b, A_log, out_w, mlp_w1, mlp_w2);
    k_ln<0><<<TOK/32, 1024>>>(x, ln1_g, ln1_b, ssm_ln_g, ssm_ln_b,
                              nullptr, nullptr, nullptr, nullptr, nullptr, nullptr, nullptr);
    k_mma<0, 256, 192><<<dim3(4, TOK/128), 256, SMEM_K>>>(nullptr, nullptr, nullptr);
    k_scan1<<<NB*NCH/4, dim3(64,4)>>>();
    k_scan2<<<64, 256>>>();
    k_mma1<<<dim3(3, TOK/128), 256, SMEM_M1>>>(out_b, D_param);
    k_ln<1><<<TOK/32, 1024>>>(x, ln2_g, ln2_b, nullptr, nullptr,
                              dw_w, bn_g, bn_b, bn_rm, bn_rv, aL, aS);
    k_mma<2, HID, 192><<<dim3(12, TOK/128), 256, SMEM_K>>>(mlp_b1, nullptr, nullptr);
    k_mma<3, 192, HID><<<dim3(3, TOK/128), 256, SMEM_K>>>(mlp_b2, aM, out);
}